// round 1
// baseline (speedup 1.0000x reference)
#include <cuda_runtime.h>
#include <math.h>

#define CB 16
#define CS 1024
#define CD 1024
#define CH 16
#define CDK 64
#define CM (CB*CS)   /* 16384 rows */

typedef unsigned long long u64;

// ---------- Blackwell packed-fp32 helpers (fma.rn.f32x2: 2x FFMA throughput) ----------
__device__ __forceinline__ u64 pack2(float lo, float hi) {
    u64 r; asm("mov.b64 %0, {%1, %2};" : "=l"(r) : "f"(lo), "f"(hi)); return r;
}
__device__ __forceinline__ void unpack2(u64 v, float& lo, float& hi) {
    asm("mov.b64 {%0, %1}, %2;" : "=f"(lo), "=f"(hi) : "l"(v));
}
__device__ __forceinline__ u64 fma2(u64 a, u64 b, u64 c) {
    u64 d; asm("fma.rn.f32x2 %0, %1, %2, %3;" : "=l"(d) : "l"(a), "l"(b), "l"(c)); return d;
}
__device__ __forceinline__ u64 mul2(u64 a, u64 b) {
    u64 d; asm("mul.rn.f32x2 %0, %1, %2;" : "=l"(d) : "l"(a), "l"(b)); return d;
}

// ---------- scratch (device globals: allocation-free) ----------
__device__ float g_q[(size_t)CM * CD];
__device__ float g_k[(size_t)CM * CD];
__device__ float g_v[(size_t)CM * CD];
__device__ float g_ctx[(size_t)CM * CD];

// =====================================================================
// SGEMM: C[M,N] = A[M,K] @ W[K,N], M=16384, N=K=1024. 128x128x8 tiles,
// 256 threads, 8x8 per thread, f32x2 accumulators.
// =====================================================================
__global__ void __launch_bounds__(256, 2) sgemm_kernel(
    const float* __restrict__ A, const float* __restrict__ W, float* __restrict__ C)
{
    const int K = CD, N = CD;
    __shared__ float As[8][128];   // transposed A tile: As[k][m]
    __shared__ float Bs[8][128];   // Bs[k][n]
    const int tid = threadIdx.x;
    const int m0 = blockIdx.y * 128;
    const int n0 = blockIdx.x * 128;

    const int arow = tid >> 1;          // 0..127
    const int acol = (tid & 1) << 2;    // 0 or 4
    const int brow = tid >> 5;          // 0..7
    const int bcol = (tid & 31) << 2;   // 0..124

    const float* Ap = A + (size_t)(m0 + arow) * K + acol;
    const float* Wp = W + (size_t)brow * N + n0 + bcol;

    const int tr = (tid >> 4) << 3;     // thread row base in tile
    const int tc = (tid & 15) << 3;     // thread col base in tile

    u64 acc[8][4];
    #pragma unroll
    for (int i = 0; i < 8; ++i) {
        #pragma unroll
        for (int j = 0; j < 4; ++j) acc[i][j] = 0ull;
    }

    // prefetch first tile into registers
    float4 av = *(const float4*)Ap;
    float4 bv = *(const float4*)Wp;

    for (int k0 = 0; k0 < K; k0 += 8) {
        __syncthreads();
        As[acol + 0][arow] = av.x;
        As[acol + 1][arow] = av.y;
        As[acol + 2][arow] = av.z;
        As[acol + 3][arow] = av.w;
        *(float4*)&Bs[brow][bcol] = bv;
        __syncthreads();
        if (k0 + 8 < K) {
            av = *(const float4*)(Ap + k0 + 8);
            bv = *(const float4*)(Wp + (size_t)(k0 + 8) * N);
        }
        #pragma unroll
        for (int kk = 0; kk < 8; ++kk) {
            float4 a0 = *(const float4*)&As[kk][tr];
            float4 a1 = *(const float4*)&As[kk][tr + 4];
            ulonglong2 bA = *(const ulonglong2*)&Bs[kk][tc];       // (b0,b1),(b2,b3)
            ulonglong2 bB = *(const ulonglong2*)&Bs[kk][tc + 4];   // (b4,b5),(b6,b7)
            float a[8] = {a0.x, a0.y, a0.z, a0.w, a1.x, a1.y, a1.z, a1.w};
            #pragma unroll
            for (int i = 0; i < 8; ++i) {
                u64 aa = pack2(a[i], a[i]);
                acc[i][0] = fma2(aa, bA.x, acc[i][0]);
                acc[i][1] = fma2(aa, bA.y, acc[i][1]);
                acc[i][2] = fma2(aa, bB.x, acc[i][2]);
                acc[i][3] = fma2(aa, bB.y, acc[i][3]);
            }
        }
    }

    #pragma unroll
    for (int i = 0; i < 8; ++i) {
        float o[8];
        unpack2(acc[i][0], o[0], o[1]);
        unpack2(acc[i][1], o[2], o[3]);
        unpack2(acc[i][2], o[4], o[5]);
        unpack2(acc[i][3], o[6], o[7]);
        float* Cp = C + (size_t)(m0 + tr + i) * N + n0 + tc;
        *(float4*)Cp       = make_float4(o[0], o[1], o[2], o[3]);
        *(float4*)(Cp + 4) = make_float4(o[4], o[5], o[6], o[7]);
    }
}

// =====================================================================
// Flash attention: one CTA per (64-query tile, head, batch).
// Q,K,V in [B,S,H*DK] layout (straight GEMM output). Online softmax.
// Output ctx in [B,S,H,DK] ( == [B,S,H*DK] row-major ).
// =====================================================================
#define SSTR 68                      /* smem row stride: keeps 16B alignment, kills conflicts */
#define FL_SMEM (4 * 64 * SSTR * 4)  /* 69,632 B dynamic smem */

__global__ void __launch_bounds__(256, 2) flash_kernel(
    const float* __restrict__ Q, const float* __restrict__ Kx,
    const float* __restrict__ V, const float* __restrict__ bias,
    const float* __restrict__ btr, float* __restrict__ ctx)
{
    extern __shared__ float sm[];
    float* Qs = sm;                   // [64][SSTR] row = query, col = d
    float* Ks = sm + 64 * SSTR;       // [64][SSTR] row = d, col = key (transposed)
    float* Vs = sm + 2 * 64 * SSTR;   // [64][SSTR] row = key, col = d
    float* Ps = sm + 3 * 64 * SSTR;   // [64][SSTR] row = query, col = key

    const int tid = threadIdx.x;
    const int tx = tid & 15;          // key/d micro-col group
    const int ty = tid >> 4;          // query micro-row group
    const int h  = blockIdx.y;
    const int b  = blockIdx.z;
    const int q0 = blockIdx.x * 64;

    const float bscale = btr[h];
    const float sfac = 0.125f;        // 1/sqrt(64)

    const float* Qg = Q  + (size_t)b * CS * CD + h * CDK;
    const float* Kg = Kx + (size_t)b * CS * CD + h * CDK;
    const float* Vg = V  + (size_t)b * CS * CD + h * CDK;

    // ---- load Q tile (64 x 64) ----
    {
        const int r  = tid >> 4;
        const int c4 = (tid & 15) << 2;
        #pragma unroll
        for (int p = 0; p < 4; ++p) {
            int row = r + p * 16;
            float4 qv = *(const float4*)(Qg + (size_t)(q0 + row) * CD + c4);
            *(float4*)&Qs[row * SSTR + c4] = qv;
        }
    }

    u64 o2[4][2] = {};
    float mrow[4], lrow[4];
    #pragma unroll
    for (int i = 0; i < 4; ++i) { mrow[i] = -3.0e38f; lrow[i] = 0.0f; }

    for (int kv0 = 0; kv0 < CS; kv0 += 64) {
        __syncthreads();  // prior PV done with Vs/Ps

        // ---- load K tile transposed (register 4x4 transpose, float4 writes) ----
        {
            const int br = tid >> 4, bc = tid & 15;
            float kin[4][4];
            #pragma unroll
            for (int u = 0; u < 4; ++u) {
                float4 t = *(const float4*)(Kg + (size_t)(kv0 + br * 4 + u) * CD + bc * 4);
                kin[u][0] = t.x; kin[u][1] = t.y; kin[u][2] = t.z; kin[u][3] = t.w;
            }
            #pragma unroll
            for (int vv = 0; vv < 4; ++vv) {
                *(float4*)&Ks[(bc * 4 + vv) * SSTR + br * 4] =
                    make_float4(kin[0][vv], kin[1][vv], kin[2][vv], kin[3][vv]);
            }
        }
        // ---- load V tile direct ----
        {
            const int r  = tid >> 4;
            const int c4 = (tid & 15) << 2;
            #pragma unroll
            for (int p = 0; p < 4; ++p) {
                int row = r + p * 16;
                *(float4*)&Vs[row * SSTR + c4] =
                    *(const float4*)(Vg + (size_t)(kv0 + row) * CD + c4);
            }
        }
        __syncthreads();

        // ---- scores: S[4q][4k] = Q . K^T ----
        u64 s2[4][2] = {};
        #pragma unroll 4
        for (int d4 = 0; d4 < 16; ++d4) {
            float qa[4][4];
            #pragma unroll
            for (int i = 0; i < 4; ++i) {
                float4 t = *(const float4*)&Qs[(ty * 4 + i) * SSTR + d4 * 4];
                qa[i][0] = t.x; qa[i][1] = t.y; qa[i][2] = t.z; qa[i][3] = t.w;
            }
            #pragma unroll
            for (int u = 0; u < 4; ++u) {
                ulonglong2 kk = *(const ulonglong2*)&Ks[(d4 * 4 + u) * SSTR + tx * 4];
                #pragma unroll
                for (int i = 0; i < 4; ++i) {
                    u64 qq = pack2(qa[i][u], qa[i][u]);
                    s2[i][0] = fma2(qq, kk.x, s2[i][0]);
                    s2[i][1] = fma2(qq, kk.y, s2[i][1]);
                }
            }
        }

        // ---- bias + online softmax (16-lane shfl groups share a query row) ----
        #pragma unroll
        for (int i = 0; i < 4; ++i) {
            float sc[4];
            unpack2(s2[i][0], sc[0], sc[1]);
            unpack2(s2[i][1], sc[2], sc[3]);
            const int gr = q0 + ty * 4 + i;
            float4 bz = *(const float4*)(bias + (size_t)gr * CS + kv0 + tx * 4);
            sc[0] = fmaf(bscale, bz.x, sc[0] * sfac);
            sc[1] = fmaf(bscale, bz.y, sc[1] * sfac);
            sc[2] = fmaf(bscale, bz.z, sc[2] * sfac);
            sc[3] = fmaf(bscale, bz.w, sc[3] * sfac);

            float mx = fmaxf(fmaxf(sc[0], sc[1]), fmaxf(sc[2], sc[3]));
            #pragma unroll
            for (int o = 1; o < 16; o <<= 1)
                mx = fmaxf(mx, __shfl_xor_sync(0xffffffffu, mx, o));
            float mnew = fmaxf(mrow[i], mx);
            float alpha = __expf(mrow[i] - mnew);
            mrow[i] = mnew;
            float p0 = __expf(sc[0] - mnew);
            float p1 = __expf(sc[1] - mnew);
            float p2 = __expf(sc[2] - mnew);
            float p3 = __expf(sc[3] - mnew);
            float rs = (p0 + p1) + (p2 + p3);
            #pragma unroll
            for (int o = 1; o < 16; o <<= 1)
                rs += __shfl_xor_sync(0xffffffffu, rs, o);
            lrow[i] = lrow[i] * alpha + rs;
            u64 aa = pack2(alpha, alpha);
            o2[i][0] = mul2(o2[i][0], aa);
            o2[i][1] = mul2(o2[i][1], aa);
            *(float4*)&Ps[(ty * 4 + i) * SSTR + tx * 4] = make_float4(p0, p1, p2, p3);
        }
        __syncthreads();

        // ---- O += P @ V ----
        #pragma unroll 4
        for (int k4 = 0; k4 < 16; ++k4) {
            float pa[4][4];
            #pragma unroll
            for (int i = 0; i < 4; ++i) {
                float4 t = *(const float4*)&Ps[(ty * 4 + i) * SSTR + k4 * 4];
                pa[i][0] = t.x; pa[i][1] = t.y; pa[i][2] = t.z; pa[i][3] = t.w;
            }
            #pragma unroll
            for (int u = 0; u < 4; ++u) {
                ulonglong2 vv = *(const ulonglong2*)&Vs[(k4 * 4 + u) * SSTR + tx * 4];
                #pragma unroll
                for (int i = 0; i < 4; ++i) {
                    u64 pp = pack2(pa[i][u], pa[i][u]);
                    o2[i][0] = fma2(pp, vv.x, o2[i][0]);
                    o2[i][1] = fma2(pp, vv.y, o2[i][1]);
                }
            }
        }
    }

    // ---- normalize + write ctx[b, s, h, d] ----
    #pragma unroll
    for (int i = 0; i < 4; ++i) {
        float inv = 1.0f / lrow[i];
        float o[4];
        unpack2(o2[i][0], o[0], o[1]);
        unpack2(o2[i][1], o[2], o[3]);
        const int gr = q0 + ty * 4 + i;
        float* cp = ctx + (((size_t)b * CS + gr) * CH + h) * CDK + tx * 4;
        *(float4*)cp = make_float4(o[0] * inv, o[1] * inv, o[2] * inv, o[3] * inv);
    }
}

// =====================================================================
// launch
// =====================================================================
extern "C" void kernel_launch(void* const* d_in, const int* in_sizes, int n_in,
                              void* d_out, int out_size) {
    (void)in_sizes; (void)n_in; (void)out_size;
    const float* X   = (const float*)d_in[0];
    const float* bLL = (const float*)d_in[1];
    const float* Wq  = (const float*)d_in[2];
    const float* Wk  = (const float*)d_in[3];
    const float* Wv  = (const float*)d_in[4];
    const float* Wo  = (const float*)d_in[5];
    const float* btr = (const float*)d_in[6];
    float* out = (float*)d_out;

    float *q, *k, *v, *ctx;
    cudaGetSymbolAddress((void**)&q,   g_q);
    cudaGetSymbolAddress((void**)&k,   g_k);
    cudaGetSymbolAddress((void**)&v,   g_v);
    cudaGetSymbolAddress((void**)&ctx, g_ctx);

    cudaFuncSetAttribute(flash_kernel, cudaFuncAttributeMaxDynamicSharedMemorySize, FL_SMEM);

    dim3 gg(CD / 128, CM / 128);
    sgemm_kernel<<<gg, 256>>>(X, Wq, q);
    sgemm_kernel<<<gg, 256>>>(X, Wk, k);
    sgemm_kernel<<<gg, 256>>>(X, Wv, v);
    flash_kernel<<<dim3(CS / 64, CH, CB), 256, FL_SMEM>>>(q, k, v, bLL, btr, ctx);
    sgemm_kernel<<<gg, 256>>>(ctx, Wo, out);
}

// round 3
// speedup vs baseline: 1.4548x; 1.4548x over previous
#include <cuda_runtime.h>
#include <cuda_bf16.h>
#include <math.h>
#include <cstdint>

#define CB 16
#define CS 1024
#define CD 1024
#define CH 16
#define CDK 64
#define CM (CB*CS)   /* 16384 rows */

typedef unsigned long long u64;

// =====================================================================
// helpers
// =====================================================================
__device__ __forceinline__ uint32_t smem_to_u32(const void* smem_ptr) {
    uint32_t addr;
    asm("{ .reg .u64 tmp; cvta.to.shared.u64 tmp, %1; cvt.u32.u64 %0, tmp; }"
        : "=r"(addr) : "l"(smem_ptr));
    return addr;
}
__device__ __forceinline__ void cpasync16(uint32_t dst, const void* src) {
    asm volatile("cp.async.cg.shared.global [%0], [%1], 16;\n" :: "r"(dst), "l"(src));
}
__device__ __forceinline__ void cp_commit() { asm volatile("cp.async.commit_group;" ::: "memory"); }
template<int N> __device__ __forceinline__ void cp_wait() {
    asm volatile("cp.async.wait_group %0;" :: "n"(N) : "memory");
}
__device__ __forceinline__ void ldx4(uint32_t r[4], uint32_t addr) {
    asm volatile("ldmatrix.sync.aligned.m8n8.x4.shared.b16 {%0,%1,%2,%3}, [%4];"
        : "=r"(r[0]), "=r"(r[1]), "=r"(r[2]), "=r"(r[3]) : "r"(addr));
}
__device__ __forceinline__ void mma16816(float c[4], const uint32_t a[4],
                                         uint32_t b0, uint32_t b1) {
    asm volatile(
        "mma.sync.aligned.m16n8k16.row.col.f32.bf16.bf16.f32 "
        "{%0,%1,%2,%3}, {%4,%5,%6,%7}, {%8,%9}, {%0,%1,%2,%3};"
        : "+f"(c[0]), "+f"(c[1]), "+f"(c[2]), "+f"(c[3])
        : "r"(a[0]), "r"(a[1]), "r"(a[2]), "r"(a[3]), "r"(b0), "r"(b1));
}

// ---------- fp32x2 helpers for flash kernel ----------
__device__ __forceinline__ u64 pack2(float lo, float hi) {
    u64 r; asm("mov.b64 %0, {%1, %2};" : "=l"(r) : "f"(lo), "f"(hi)); return r;
}
__device__ __forceinline__ void unpack2(u64 v, float& lo, float& hi) {
    asm("mov.b64 {%0, %1}, %2;" : "=f"(lo), "=f"(hi) : "l"(v));
}
__device__ __forceinline__ u64 fma2(u64 a, u64 b, u64 c) {
    u64 d; asm("fma.rn.f32x2 %0, %1, %2, %3;" : "=l"(d) : "l"(a), "l"(b), "l"(c)); return d;
}
__device__ __forceinline__ u64 mul2(u64 a, u64 b) {
    u64 d; asm("mul.rn.f32x2 %0, %1, %2;" : "=l"(d) : "l"(a), "l"(b)); return d;
}

// ---------- scratch (device globals: allocation-free) ----------
__device__ float g_q[(size_t)CM * CD];
__device__ float g_k[(size_t)CM * CD];
__device__ float g_v[(size_t)CM * CD];
__device__ float g_ctx[(size_t)CM * CD];
__device__ __nv_bfloat16 g_xhi[(size_t)CM * CD];
__device__ __nv_bfloat16 g_xlo[(size_t)CM * CD];
__device__ __nv_bfloat16 g_chi[(size_t)CM * CD];
__device__ __nv_bfloat16 g_clo[(size_t)CM * CD];
__device__ __nv_bfloat16 g_wthi[(size_t)CD * CD];
__device__ __nv_bfloat16 g_wtlo[(size_t)CD * CD];

// =====================================================================
// fp32 -> split bf16 (hi + residual lo), vectorized
// =====================================================================
__global__ void split_kernel(const float4* __restrict__ x,
                             __nv_bfloat162* __restrict__ hi,
                             __nv_bfloat162* __restrict__ lo, int n4) {
    int i = blockIdx.x * blockDim.x + threadIdx.x;
    if (i >= n4) return;
    float4 v = x[i];
    __nv_bfloat16 h0 = __float2bfloat16_rn(v.x);
    __nv_bfloat16 h1 = __float2bfloat16_rn(v.y);
    __nv_bfloat16 h2 = __float2bfloat16_rn(v.z);
    __nv_bfloat16 h3 = __float2bfloat16_rn(v.w);
    __nv_bfloat16 l0 = __float2bfloat16_rn(v.x - __bfloat162float(h0));
    __nv_bfloat16 l1 = __float2bfloat16_rn(v.y - __bfloat162float(h1));
    __nv_bfloat16 l2 = __float2bfloat16_rn(v.z - __bfloat162float(h2));
    __nv_bfloat16 l3 = __float2bfloat16_rn(v.w - __bfloat162float(h3));
    __nv_bfloat162 a; a.x = h0; a.y = h1;
    __nv_bfloat162 b; b.x = h2; b.y = h3;
    __nv_bfloat162 c; c.x = l0; c.y = l1;
    __nv_bfloat162 d; d.x = l2; d.y = l3;
    hi[2*i] = a; hi[2*i+1] = b;
    lo[2*i] = c; lo[2*i+1] = d;
}

// =====================================================================
// W[K,N] fp32 -> transposed split bf16 T[N,K] (hi, lo)
// =====================================================================
__global__ void tsplit_kernel(const float* __restrict__ W,
                              __nv_bfloat16* __restrict__ Thi,
                              __nv_bfloat16* __restrict__ Tlo) {
    __shared__ float t[32][33];
    int n0 = blockIdx.x * 32, k0 = blockIdx.y * 32;
    int tx = threadIdx.x, ty = threadIdx.y;   // 32 x 8
    #pragma unroll
    for (int j = 0; j < 4; ++j)
        t[ty + 8*j][tx] = W[(size_t)(k0 + ty + 8*j) * CD + n0 + tx];
    __syncthreads();
    #pragma unroll
    for (int j = 0; j < 4; ++j) {
        float v = t[tx][ty + 8*j];
        __nv_bfloat16 h = __float2bfloat16_rn(v);
        __nv_bfloat16 l = __float2bfloat16_rn(v - __bfloat162float(h));
        size_t o = (size_t)(n0 + ty + 8*j) * CD + k0 + tx;
        Thi[o] = h; Tlo[o] = l;
    }
}

// =====================================================================
// mma.sync bf16 split GEMM: C[M,N] = Afp32 @ Bfp32
//   A as (Ahi,Alo)[M,K] bf16 row-major; B as (Bhi,Blo)[N,K] bf16 row-major (B^T).
// Block 128x128x32, 8 warps (2x4), warp tile 64x32, double-buffered cp.async.
// =====================================================================
#define ROWB 80                 /* padded smem row: 32 bf16 = 64B data + 16B pad */
#define ASTG (128 * ROWB)       /* 10240 B per sub-tile */
#define STG  (4 * ASTG)         /* Ah,Al,Bh,Bl = 40960 B per stage */
#define GSMEM (2 * STG)         /* 81920 B */

__device__ __forceinline__ void gm_load_stage(
    uint32_t sb, int s,
    const __nv_bfloat16* __restrict__ Ahi, const __nv_bfloat16* __restrict__ Alo,
    const __nv_bfloat16* __restrict__ Bhi, const __nv_bfloat16* __restrict__ Blo,
    int tid, int m0, int n0, int k0)
{
    uint32_t base = sb + (uint32_t)s * STG;
    #pragma unroll
    for (int j = 0; j < 2; ++j) {
        int c = tid + j * 256;          // 0..511
        int row = c >> 2, kc = c & 3;
        uint32_t d = base + row * ROWB + kc * 16;
        size_t g = (size_t)(m0 + row) * CD + k0 + kc * 8;
        cpasync16(d, Ahi + g);
        cpasync16(d + ASTG, Alo + g);
    }
    #pragma unroll
    for (int j = 0; j < 2; ++j) {
        int c = tid + j * 256;
        int row = c >> 2, kc = c & 3;
        uint32_t d = base + 2 * ASTG + row * ROWB + kc * 16;
        size_t g = (size_t)(n0 + row) * CD + k0 + kc * 8;
        cpasync16(d, Bhi + g);
        cpasync16(d + ASTG, Blo + g);
    }
    cp_commit();
}

__global__ void __launch_bounds__(256, 1) gemm_mma_kernel(
    const __nv_bfloat16* __restrict__ Ahi, const __nv_bfloat16* __restrict__ Alo,
    const __nv_bfloat16* __restrict__ Bhi, const __nv_bfloat16* __restrict__ Blo,
    float* __restrict__ C)
{
    extern __shared__ __align__(128) char smem[];
    const uint32_t sb = smem_to_u32(smem);
    const int tid = threadIdx.x;
    const int lane = tid & 31, wid = tid >> 5;
    const int m0 = blockIdx.y * 128;
    const int n0 = blockIdx.x * 128;
    const int wm0 = (wid & 1) * 64;
    const int wn0 = (wid >> 1) * 32;

    float acc[4][4][4];
    #pragma unroll
    for (int i = 0; i < 4; ++i)
        #pragma unroll
        for (int j = 0; j < 4; ++j)
            #pragma unroll
            for (int q = 0; q < 4; ++q) acc[i][j][q] = 0.0f;

    gm_load_stage(sb, 0, Ahi, Alo, Bhi, Blo, tid, m0, n0, 0);
    gm_load_stage(sb, 1, Ahi, Alo, Bhi, Blo, tid, m0, n0, 32);

    const int lr = lane & 15;
    const int lc = (lane & 16) ? 16 : 0;

    for (int i = 0; i < 32; ++i) {
        const int s = i & 1;
        if (i < 31) cp_wait<1>(); else cp_wait<0>();
        __syncthreads();

        const uint32_t base = sb + (uint32_t)s * STG;
        #pragma unroll
        for (int kk = 0; kk < 2; ++kk) {
            uint32_t afh[4][4], afl[4][4];
            uint32_t bh[4][2], bl[4][2];
            #pragma unroll
            for (int mi = 0; mi < 4; ++mi) {
                uint32_t ad = base + (wm0 + mi * 16 + lr) * ROWB + kk * 32 + lc;
                ldx4(afh[mi], ad);
                ldx4(afl[mi], ad + ASTG);
            }
            #pragma unroll
            for (int np = 0; np < 2; ++np) {
                uint32_t bd = base + 2 * ASTG + (wn0 + np * 16 + lr) * ROWB + kk * 32 + lc;
                uint32_t r[4];
                ldx4(r, bd);
                bh[np*2][0] = r[0]; bh[np*2][1] = r[2];
                bh[np*2+1][0] = r[1]; bh[np*2+1][1] = r[3];
                ldx4(r, bd + ASTG);
                bl[np*2][0] = r[0]; bl[np*2][1] = r[2];
                bl[np*2+1][0] = r[1]; bl[np*2+1][1] = r[3];
            }
            #pragma unroll
            for (int mi = 0; mi < 4; ++mi)
                #pragma unroll
                for (int ni = 0; ni < 4; ++ni) {
                    mma16816(acc[mi][ni], afh[mi], bh[ni][0], bh[ni][1]);
                    mma16816(acc[mi][ni], afh[mi], bl[ni][0], bl[ni][1]);
                    mma16816(acc[mi][ni], afl[mi], bh[ni][0], bh[ni][1]);
                }
        }
        __syncthreads();
        if (i + 2 < 32)
            gm_load_stage(sb, s, Ahi, Alo, Bhi, Blo, tid, m0, n0, (i + 2) * 32);
    }

    // epilogue: direct fp32 stores
    #pragma unroll
    for (int mi = 0; mi < 4; ++mi) {
        #pragma unroll
        for (int ni = 0; ni < 4; ++ni) {
            int r0 = m0 + wm0 + mi * 16 + (lane >> 2);
            int c0 = n0 + wn0 + ni * 8 + (lane & 3) * 2;
            *(float2*)&C[(size_t)r0 * CD + c0] = make_float2(acc[mi][ni][0], acc[mi][ni][1]);
            *(float2*)&C[(size_t)(r0 + 8) * CD + c0] = make_float2(acc[mi][ni][2], acc[mi][ni][3]);
        }
    }
}

// =====================================================================
// Flash attention (unchanged): fp32x2, one CTA per (64-query tile, head, batch)
// =====================================================================
#define SSTR 68
#define FL_SMEM (4 * 64 * SSTR * 4)

__global__ void __launch_bounds__(256, 2) flash_kernel(
    const float* __restrict__ Q, const float* __restrict__ Kx,
    const float* __restrict__ V, const float* __restrict__ bias,
    const float* __restrict__ btr, float* __restrict__ ctx)
{
    extern __shared__ float sm[];
    float* Qs = sm;
    float* Ks = sm + 64 * SSTR;
    float* Vs = sm + 2 * 64 * SSTR;
    float* Ps = sm + 3 * 64 * SSTR;

    const int tid = threadIdx.x;
    const int tx = tid & 15;
    const int ty = tid >> 4;
    const int h  = blockIdx.y;
    const int b  = blockIdx.z;
    const int q0 = blockIdx.x * 64;

    const float bscale = btr[h];
    const float sfac = 0.125f;

    const float* Qg = Q  + (size_t)b * CS * CD + h * CDK;
    const float* Kg = Kx + (size_t)b * CS * CD + h * CDK;
    const float* Vg = V  + (size_t)b * CS * CD + h * CDK;

    {
        const int r  = tid >> 4;
        const int c4 = (tid & 15) << 2;
        #pragma unroll
        for (int p = 0; p < 4; ++p) {
            int row = r + p * 16;
            float4 qv = *(const float4*)(Qg + (size_t)(q0 + row) * CD + c4);
            *(float4*)&Qs[row * SSTR + c4] = qv;
        }
    }

    u64 o2[4][2] = {};
    float mrow[4], lrow[4];
    #pragma unroll
    for (int i = 0; i < 4; ++i) { mrow[i] = -3.0e38f; lrow[i] = 0.0f; }

    for (int kv0 = 0; kv0 < CS; kv0 += 64) {
        __syncthreads();
        {
            const int br = tid >> 4, bc = tid & 15;
            float kin[4][4];
            #pragma unroll
            for (int u = 0; u < 4; ++u) {
                float4 t = *(const float4*)(Kg + (size_t)(kv0 + br * 4 + u) * CD + bc * 4);
                kin[u][0] = t.x; kin[u][1] = t.y; kin[u][2] = t.z; kin[u][3] = t.w;
            }
            #pragma unroll
            for (int vv = 0; vv < 4; ++vv) {
                *(float4*)&Ks[(bc * 4 + vv) * SSTR + br * 4] =
                    make_float4(kin[0][vv], kin[1][vv], kin[2][vv], kin[3][vv]);
            }
        }
        {
            const int r  = tid >> 4;
            const int c4 = (tid & 15) << 2;
            #pragma unroll
            for (int p = 0; p < 4; ++p) {
                int row = r + p * 16;
                *(float4*)&Vs[row * SSTR + c4] =
                    *(const float4*)(Vg + (size_t)(kv0 + row) * CD + c4);
            }
        }
        __syncthreads();

        u64 s2[4][2] = {};
        #pragma unroll 4
        for (int d4 = 0; d4 < 16; ++d4) {
            float qa[4][4];
            #pragma unroll
            for (int i = 0; i < 4; ++i) {
                float4 t = *(const float4*)&Qs[(ty * 4 + i) * SSTR + d4 * 4];
                qa[i][0] = t.x; qa[i][1] = t.y; qa[i][2] = t.z; qa[i][3] = t.w;
            }
            #pragma unroll
            for (int u = 0; u < 4; ++u) {
                ulonglong2 kk = *(const ulonglong2*)&Ks[(d4 * 4 + u) * SSTR + tx * 4];
                #pragma unroll
                for (int i = 0; i < 4; ++i) {
                    u64 qq = pack2(qa[i][u], qa[i][u]);
                    s2[i][0] = fma2(qq, kk.x, s2[i][0]);
                    s2[i][1] = fma2(qq, kk.y, s2[i][1]);
                }
            }
        }

        #pragma unroll
        for (int i = 0; i < 4; ++i) {
            float sc[4];
            unpack2(s2[i][0], sc[0], sc[1]);
            unpack2(s2[i][1], sc[2], sc[3]);
            const int gr = q0 + ty * 4 + i;
            float4 bz = *(const float4*)(bias + (size_t)gr * CS + kv0 + tx * 4);
            sc[0] = fmaf(bscale, bz.x, sc[0] * sfac);
            sc[1] = fmaf(bscale, bz.y, sc[1] * sfac);
            sc[2] = fmaf(bscale, bz.z, sc[2] * sfac);
            sc[3] = fmaf(bscale, bz.w, sc[3] * sfac);

            float mx = fmaxf(fmaxf(sc[0], sc[1]), fmaxf(sc[2], sc[3]));
            #pragma unroll
            for (int o = 1; o < 16; o <<= 1)
                mx = fmaxf(mx, __shfl_xor_sync(0xffffffffu, mx, o));
            float mnew = fmaxf(mrow[i], mx);
            float alpha = __expf(mrow[i] - mnew);
            mrow[i] = mnew;
            float p0 = __expf(sc[0] - mnew);
            float p1 = __expf(sc[1] - mnew);
            float p2 = __expf(sc[2] - mnew);
            float p3 = __expf(sc[3] - mnew);
            float rs = (p0 + p1) + (p2 + p3);
            #pragma unroll
            for (int o = 1; o < 16; o <<= 1)
                rs += __shfl_xor_sync(0xffffffffu, rs, o);
            lrow[i] = lrow[i] * alpha + rs;
            u64 aa = pack2(alpha, alpha);
            o2[i][0] = mul2(o2[i][0], aa);
            o2[i][1] = mul2(o2[i][1], aa);
            *(float4*)&Ps[(ty * 4 + i) * SSTR + tx * 4] = make_float4(p0, p1, p2, p3);
        }
        __syncthreads();

        #pragma unroll 4
        for (int k4 = 0; k4 < 16; ++k4) {
            float pa[4][4];
            #pragma unroll
            for (int i = 0; i < 4; ++i) {
                float4 t = *(const float4*)&Ps[(ty * 4 + i) * SSTR + k4 * 4];
                pa[i][0] = t.x; pa[i][1] = t.y; pa[i][2] = t.z; pa[i][3] = t.w;
            }
            #pragma unroll
            for (int u = 0; u < 4; ++u) {
                ulonglong2 vv = *(const ulonglong2*)&Vs[(k4 * 4 + u) * SSTR + tx * 4];
                #pragma unroll
                for (int i = 0; i < 4; ++i) {
                    u64 pp = pack2(pa[i][u], pa[i][u]);
                    o2[i][0] = fma2(pp, vv.x, o2[i][0]);
                    o2[i][1] = fma2(pp, vv.y, o2[i][1]);
                }
            }
        }
    }

    #pragma unroll
    for (int i = 0; i < 4; ++i) {
        float inv = 1.0f / lrow[i];
        float o[4];
        unpack2(o2[i][0], o[0], o[1]);
        unpack2(o2[i][1], o[2], o[3]);
        const int gr = q0 + ty * 4 + i;
        float* cp = ctx + (((size_t)b * CS + gr) * CH + h) * CDK + tx * 4;
        *(float4*)cp = make_float4(o[0] * inv, o[1] * inv, o[2] * inv, o[3] * inv);
    }
}

// =====================================================================
// launch
// =====================================================================
extern "C" void kernel_launch(void* const* d_in, const int* in_sizes, int n_in,
                              void* d_out, int out_size) {
    (void)in_sizes; (void)n_in; (void)out_size;
    const float* X   = (const float*)d_in[0];
    const float* bLL = (const float*)d_in[1];
    const float* Wq  = (const float*)d_in[2];
    const float* Wk  = (const float*)d_in[3];
    const float* Wv  = (const float*)d_in[4];
    const float* Wo  = (const float*)d_in[5];
    const float* btr = (const float*)d_in[6];
    float* out = (float*)d_out;

    float *q, *k, *v, *ctx;
    __nv_bfloat16 *xhi, *xlo, *chi, *clo, *wthi, *wtlo;
    cudaGetSymbolAddress((void**)&q,    g_q);
    cudaGetSymbolAddress((void**)&k,    g_k);
    cudaGetSymbolAddress((void**)&v,    g_v);
    cudaGetSymbolAddress((void**)&ctx,  g_ctx);
    cudaGetSymbolAddress((void**)&xhi,  g_xhi);
    cudaGetSymbolAddress((void**)&xlo,  g_xlo);
    cudaGetSymbolAddress((void**)&chi,  g_chi);
    cudaGetSymbolAddress((void**)&clo,  g_clo);
    cudaGetSymbolAddress((void**)&wthi, g_wthi);
    cudaGetSymbolAddress((void**)&wtlo, g_wtlo);

    cudaFuncSetAttribute(gemm_mma_kernel, cudaFuncAttributeMaxDynamicSharedMemorySize, GSMEM);
    cudaFuncSetAttribute(flash_kernel, cudaFuncAttributeMaxDynamicSharedMemorySize, FL_SMEM);

    const int n4x = (CM * CD) / 4;
    const dim3 tsg(32, 32), tsb(32, 8);
    const dim3 gg(CD / 128, CM / 128);   // (8, 128)

    // X -> split bf16
    split_kernel<<<(n4x + 255) / 256, 256>>>((const float4*)X,
        (__nv_bfloat162*)xhi, (__nv_bfloat162*)xlo, n4x);

    // Q/K/V projections
    tsplit_kernel<<<tsg, tsb>>>(Wq, wthi, wtlo);
    gemm_mma_kernel<<<gg, 256, GSMEM>>>(xhi, xlo, wthi, wtlo, q);
    tsplit_kernel<<<tsg, tsb>>>(Wk, wthi, wtlo);
    gemm_mma_kernel<<<gg, 256, GSMEM>>>(xhi, xlo, wthi, wtlo, k);
    tsplit_kernel<<<tsg, tsb>>>(Wv, wthi, wtlo);
    gemm_mma_kernel<<<gg, 256, GSMEM>>>(xhi, xlo, wthi, wtlo, v);

    // attention
    flash_kernel<<<dim3(CS / 64, CH, CB), 256, FL_SMEM>>>(q, k, v, bLL, btr, ctx);

    // output projection
    split_kernel<<<(n4x + 255) / 256, 256>>>((const float4*)ctx,
        (__nv_bfloat162*)chi, (__nv_bfloat162*)clo, n4x);
    tsplit_kernel<<<tsg, tsb>>>(Wo, wthi, wtlo);
    gemm_mma_kernel<<<gg, 256, GSMEM>>>(chi, clo, wthi, wtlo, out);
}

// round 7
// speedup vs baseline: 2.2342x; 1.5357x over previous
#include <cuda_runtime.h>
#include <cuda_bf16.h>
#include <math.h>
#include <cstdint>

#define CB 16
#define CS 1024
#define CD 1024
#define CH 16
#define CDK 64
#define CM (CB*CS)   /* 16384 rows */

// =====================================================================
// helpers
// =====================================================================
__device__ __forceinline__ uint32_t smem_to_u32(const void* smem_ptr) {
    uint32_t addr;
    asm("{ .reg .u64 tmp; cvta.to.shared.u64 tmp, %1; cvt.u32.u64 %0, tmp; }"
        : "=r"(addr) : "l"(smem_ptr));
    return addr;
}
__device__ __forceinline__ void cpasync16(uint32_t dst, const void* src) {
    asm volatile("cp.async.cg.shared.global [%0], [%1], 16;\n" :: "r"(dst), "l"(src));
}
__device__ __forceinline__ void cp_commit() { asm volatile("cp.async.commit_group;" ::: "memory"); }
template<int N> __device__ __forceinline__ void cp_wait() {
    asm volatile("cp.async.wait_group %0;" :: "n"(N) : "memory");
}
__device__ __forceinline__ void ldx4(uint32_t r[4], uint32_t addr) {
    asm volatile("ldmatrix.sync.aligned.m8n8.x4.shared.b16 {%0,%1,%2,%3}, [%4];"
        : "=r"(r[0]), "=r"(r[1]), "=r"(r[2]), "=r"(r[3]) : "r"(addr));
}
__device__ __forceinline__ void ldx4t(uint32_t r[4], uint32_t addr) {
    asm volatile("ldmatrix.sync.aligned.m8n8.x4.trans.shared.b16 {%0,%1,%2,%3}, [%4];"
        : "=r"(r[0]), "=r"(r[1]), "=r"(r[2]), "=r"(r[3]) : "r"(addr));
}
__device__ __forceinline__ void mma16816(float c[4], const uint32_t a[4],
                                         uint32_t b0, uint32_t b1) {
    asm volatile(
        "mma.sync.aligned.m16n8k16.row.col.f32.bf16.bf16.f32 "
        "{%0,%1,%2,%3}, {%4,%5,%6,%7}, {%8,%9}, {%0,%1,%2,%3};"
        : "+f"(c[0]), "+f"(c[1]), "+f"(c[2]), "+f"(c[3])
        : "r"(a[0]), "r"(a[1]), "r"(a[2]), "r"(a[3]), "r"(b0), "r"(b1));
}
// pack (x,y) into bf16x2 hi-part + residual lo-part
__device__ __forceinline__ void split2(float x, float y, uint32_t& h, uint32_t& l) {
    uint32_t hp;
    asm("cvt.rn.bf16x2.f32 %0, %1, %2;" : "=r"(hp) : "f"(y), "f"(x));
    float fx = __uint_as_float(hp << 16);
    float fy = __uint_as_float(hp & 0xffff0000u);
    uint32_t lp;
    asm("cvt.rn.bf16x2.f32 %0, %1, %2;" : "=r"(lp) : "f"(y - fy), "f"(x - fx));
    h = hp; l = lp;
}

// ---------- scratch (device globals: allocation-free) ----------
__device__ __nv_bfloat16 g_xhi[(size_t)CM * CD];
__device__ __nv_bfloat16 g_xlo[(size_t)CM * CD];
__device__ __nv_bfloat16 g_qhi[(size_t)CM * CD];
__device__ __nv_bfloat16 g_qlo[(size_t)CM * CD];
__device__ __nv_bfloat16 g_khi[(size_t)CM * CD];
__device__ __nv_bfloat16 g_klo[(size_t)CM * CD];
__device__ __nv_bfloat16 g_vhi[(size_t)CM * CD];
__device__ __nv_bfloat16 g_vlo[(size_t)CM * CD];
__device__ __nv_bfloat16 g_chi[(size_t)CM * CD];
__device__ __nv_bfloat16 g_clo[(size_t)CM * CD];
__device__ __nv_bfloat16 g_wthi[(size_t)CD * CD];
__device__ __nv_bfloat16 g_wtlo[(size_t)CD * CD];

// =====================================================================
// fp32 -> split bf16 (hi + residual lo), vectorized
// =====================================================================
__global__ void split_kernel(const float4* __restrict__ x,
                             uint32_t* __restrict__ hi,
                             uint32_t* __restrict__ lo, int n4) {
    int i = blockIdx.x * blockDim.x + threadIdx.x;
    if (i >= n4) return;
    float4 v = x[i];
    uint32_t h0, l0, h1, l1;
    split2(v.x, v.y, h0, l0);
    split2(v.z, v.w, h1, l1);
    hi[2*i] = h0; hi[2*i+1] = h1;
    lo[2*i] = l0; lo[2*i+1] = l1;
}

// =====================================================================
// W[K,N] fp32 -> transposed split bf16 T[N,K] (hi, lo)
// =====================================================================
__global__ void tsplit_kernel(const float* __restrict__ W,
                              __nv_bfloat16* __restrict__ Thi,
                              __nv_bfloat16* __restrict__ Tlo) {
    __shared__ float t[32][33];
    int n0 = blockIdx.x * 32, k0 = blockIdx.y * 32;
    int tx = threadIdx.x, ty = threadIdx.y;   // 32 x 8
    #pragma unroll
    for (int j = 0; j < 4; ++j)
        t[ty + 8*j][tx] = W[(size_t)(k0 + ty + 8*j) * CD + n0 + tx];
    __syncthreads();
    #pragma unroll
    for (int j = 0; j < 4; ++j) {
        float v = t[tx][ty + 8*j];
        __nv_bfloat16 h = __float2bfloat16_rn(v);
        __nv_bfloat16 l = __float2bfloat16_rn(v - __bfloat162float(h));
        size_t o = (size_t)(n0 + ty + 8*j) * CD + k0 + tx;
        Thi[o] = h; Tlo[o] = l;
    }
}

// =====================================================================
// mma.sync bf16 split GEMM: C = Afp32 @ Bfp32 (3-term emulation)
// Block 128x128x32, 8 warps (2x4), warp tile 64x32, double-buffered cp.async.
// SPLIT=true: write split bf16 outputs (Chl_hi/Chl_lo); else fp32 (Cf).
// =====================================================================
#define ROWB 80
#define ASTG (128 * ROWB)
#define STG  (4 * ASTG)
#define GSMEM (2 * STG)

__device__ __forceinline__ void gm_load_stage(
    uint32_t sb, int s,
    const __nv_bfloat16* __restrict__ Ahi, const __nv_bfloat16* __restrict__ Alo,
    const __nv_bfloat16* __restrict__ Bhi, const __nv_bfloat16* __restrict__ Blo,
    int tid, int m0, int n0, int k0)
{
    uint32_t base = sb + (uint32_t)s * STG;
    #pragma unroll
    for (int j = 0; j < 2; ++j) {
        int c = tid + j * 256;
        int row = c >> 2, kc = c & 3;
        uint32_t d = base + row * ROWB + kc * 16;
        size_t g = (size_t)(m0 + row) * CD + k0 + kc * 8;
        cpasync16(d, Ahi + g);
        cpasync16(d + ASTG, Alo + g);
    }
    #pragma unroll
    for (int j = 0; j < 2; ++j) {
        int c = tid + j * 256;
        int row = c >> 2, kc = c & 3;
        uint32_t d = base + 2 * ASTG + row * ROWB + kc * 16;
        size_t g = (size_t)(n0 + row) * CD + k0 + kc * 8;
        cpasync16(d, Bhi + g);
        cpasync16(d + ASTG, Blo + g);
    }
    cp_commit();
}

template<bool SPLIT>
__global__ void __launch_bounds__(256, 1) gemm_mma_kernel(
    const __nv_bfloat16* __restrict__ Ahi, const __nv_bfloat16* __restrict__ Alo,
    const __nv_bfloat16* __restrict__ Bhi, const __nv_bfloat16* __restrict__ Blo,
    float* __restrict__ Cf,
    __nv_bfloat16* __restrict__ Chi, __nv_bfloat16* __restrict__ Clo)
{
    extern __shared__ __align__(128) char smem[];
    const uint32_t sb = smem_to_u32(smem);
    const int tid = threadIdx.x;
    const int lane = tid & 31, wid = tid >> 5;
    const int m0 = blockIdx.y * 128;
    const int n0 = blockIdx.x * 128;
    const int wm0 = (wid & 1) * 64;
    const int wn0 = (wid >> 1) * 32;

    float acc[4][4][4];
    #pragma unroll
    for (int i = 0; i < 4; ++i)
        #pragma unroll
        for (int j = 0; j < 4; ++j)
            #pragma unroll
            for (int q = 0; q < 4; ++q) acc[i][j][q] = 0.0f;

    gm_load_stage(sb, 0, Ahi, Alo, Bhi, Blo, tid, m0, n0, 0);
    gm_load_stage(sb, 1, Ahi, Alo, Bhi, Blo, tid, m0, n0, 32);

    const int lr = lane & 15;
    const int lc = (lane & 16) ? 16 : 0;

    for (int i = 0; i < 32; ++i) {
        const int s = i & 1;
        if (i < 31) cp_wait<1>(); else cp_wait<0>();
        __syncthreads();

        const uint32_t base = sb + (uint32_t)s * STG;
        #pragma unroll
        for (int kk = 0; kk < 2; ++kk) {
            uint32_t afh[4][4], afl[4][4];
            uint32_t bh[4][2], bl[4][2];
            #pragma unroll
            for (int mi = 0; mi < 4; ++mi) {
                uint32_t ad = base + (wm0 + mi * 16 + lr) * ROWB + kk * 32 + lc;
                ldx4(afh[mi], ad);
                ldx4(afl[mi], ad + ASTG);
            }
            #pragma unroll
            for (int np = 0; np < 2; ++np) {
                uint32_t bd = base + 2 * ASTG + (wn0 + np * 16 + lr) * ROWB + kk * 32 + lc;
                uint32_t r[4];
                ldx4(r, bd);
                bh[np*2][0] = r[0]; bh[np*2][1] = r[2];
                bh[np*2+1][0] = r[1]; bh[np*2+1][1] = r[3];
                ldx4(r, bd + ASTG);
                bl[np*2][0] = r[0]; bl[np*2][1] = r[2];
                bl[np*2+1][0] = r[1]; bl[np*2+1][1] = r[3];
            }
            #pragma unroll
            for (int mi = 0; mi < 4; ++mi)
                #pragma unroll
                for (int ni = 0; ni < 4; ++ni) {
                    mma16816(acc[mi][ni], afh[mi], bh[ni][0], bh[ni][1]);
                    mma16816(acc[mi][ni], afh[mi], bl[ni][0], bl[ni][1]);
                    mma16816(acc[mi][ni], afl[mi], bh[ni][0], bh[ni][1]);
                }
        }
        __syncthreads();
        if (i + 2 < 32)
            gm_load_stage(sb, s, Ahi, Alo, Bhi, Blo, tid, m0, n0, (i + 2) * 32);
    }

    #pragma unroll
    for (int mi = 0; mi < 4; ++mi) {
        #pragma unroll
        for (int ni = 0; ni < 4; ++ni) {
            int r0 = m0 + wm0 + mi * 16 + (lane >> 2);
            int c0 = n0 + wn0 + ni * 8 + (lane & 3) * 2;
            if (!SPLIT) {
                *(float2*)&Cf[(size_t)r0 * CD + c0] = make_float2(acc[mi][ni][0], acc[mi][ni][1]);
                *(float2*)&Cf[(size_t)(r0 + 8) * CD + c0] = make_float2(acc[mi][ni][2], acc[mi][ni][3]);
            } else {
                uint32_t h, l;
                split2(acc[mi][ni][0], acc[mi][ni][1], h, l);
                *(uint32_t*)&Chi[(size_t)r0 * CD + c0] = h;
                *(uint32_t*)&Clo[(size_t)r0 * CD + c0] = l;
                split2(acc[mi][ni][2], acc[mi][ni][3], h, l);
                *(uint32_t*)&Chi[(size_t)(r0 + 8) * CD + c0] = h;
                *(uint32_t*)&Clo[(size_t)(r0 + 8) * CD + c0] = l;
            }
        }
    }
}

// =====================================================================
// Tensor-core flash attention (split bf16, 3-term):
// one CTA per (128-query tile, head, batch); 8 warps x 16 q rows.
// KV 64-key tiles double-buffered via cp.async. Outputs split bf16 ctx.
// =====================================================================
#define FPB 144                   /* smem pitch bytes (72 bf16) */
#define FTB (64 * FPB)            /* 9216 B per 64-row tile */
#define QTB (128 * FPB)           /* 18432 B per 128-row Q tile */
#define FL_SMEM (2*QTB + 8*FTB)   /* 110592 B */

__global__ void __launch_bounds__(256, 2) flasht_kernel(
    const __nv_bfloat16* __restrict__ Qhi, const __nv_bfloat16* __restrict__ Qlo,
    const __nv_bfloat16* __restrict__ Khi, const __nv_bfloat16* __restrict__ Klo,
    const __nv_bfloat16* __restrict__ Vhi, const __nv_bfloat16* __restrict__ Vlo,
    const float* __restrict__ bias, const float* __restrict__ btr,
    __nv_bfloat16* __restrict__ Chi, __nv_bfloat16* __restrict__ Clo)
{
    extern __shared__ __align__(128) char smem[];
    const uint32_t sb = smem_to_u32(smem);
    const uint32_t sQh = sb, sQl = sb + QTB;
    const uint32_t sKV = sb + 2 * QTB;

    const int tid = threadIdx.x, lane = tid & 31, wid = tid >> 5;
    const int h = blockIdx.y, b = blockIdx.z;
    const int q0 = blockIdx.x * 128;
    const int wq0 = wid * 16;
    const float bscale = btr[h];
    const float sfac = 0.125f;

    const size_t bh_off = (size_t)b * CS * CD + (size_t)h * CDK;
    const __nv_bfloat16* Qgh = Qhi + bh_off + (size_t)q0 * CD;
    const __nv_bfloat16* Qgl = Qlo + bh_off + (size_t)q0 * CD;
    const __nv_bfloat16* Kgh = Khi + bh_off;
    const __nv_bfloat16* Kgl = Klo + bh_off;
    const __nv_bfloat16* Vgh = Vhi + bh_off;
    const __nv_bfloat16* Vgl = Vlo + bh_off;

    // ---- Q tile load (128 rows x 128B, hi+lo) ----
    #pragma unroll
    for (int j = 0; j < 4; ++j) {
        int ch = tid + j * 256;          // 0..1023
        int row = ch >> 3, c = ch & 7;
        size_t g = (size_t)row * CD + c * 8;
        uint32_t d = sQh + row * FPB + c * 16;
        cpasync16(d, Qgh + g);
        cpasync16(d + QTB, Qgl + g);
    }
    cp_commit();

    // ---- KV stage loader ----
    auto kv_load = [&](int s, int kv0) {
        uint32_t stg = sKV + (uint32_t)s * 4 * FTB;
        #pragma unroll
        for (int j = 0; j < 2; ++j) {
            int ch = tid + j * 256;       // 0..511
            int row = ch >> 3, c = ch & 7;
            size_t g = (size_t)(kv0 + row) * CD + c * 8;
            uint32_t d = stg + row * FPB + c * 16;
            cpasync16(d,           Kgh + g);
            cpasync16(d + FTB,     Kgl + g);
            cpasync16(d + 2*FTB,   Vgh + g);
            cpasync16(d + 3*FTB,   Vgl + g);
        }
        cp_commit();
    };
    kv_load(0, 0);
    kv_load(1, 64);

    const int lr = lane & 15;
    const uint32_t lc = (lane & 16) ? 16u : 0u;
    const int rl = lane >> 2;

    float o[8][4];
    #pragma unroll
    for (int n = 0; n < 8; ++n)
        #pragma unroll
        for (int q = 0; q < 4; ++q) o[n][q] = 0.0f;
    float m_lo = -3.0e38f, m_hi = -3.0e38f, l_lo = 0.0f, l_hi = 0.0f;

    const float* b_lo = bias + (size_t)(q0 + wq0 + rl) * CS + 2 * (lane & 3);
    const float* b_hi = b_lo + 8 * CS;

    for (int it = 0; it < 16; ++it) {
        const int s = it & 1;
        if (it < 14) cp_wait<1>(); else cp_wait<0>();
        __syncthreads();
        const uint32_t stg = sKV + (uint32_t)s * 4 * FTB;
        const int kv0 = it * 64;

        // ---- scores: S = Q K^T (split 3-term) ----
        float sf[8][4];
        #pragma unroll
        for (int n = 0; n < 8; ++n)
            #pragma unroll
            for (int q = 0; q < 4; ++q) sf[n][q] = 0.0f;

        #pragma unroll
        for (int kk = 0; kk < 4; ++kk) {
            uint32_t qhk[4], qlk[4];
            uint32_t qad = sQh + (wq0 + lr) * FPB + kk * 32 + lc;
            ldx4(qhk, qad);
            ldx4(qlk, qad + QTB);
            #pragma unroll
            for (int np = 0; np < 4; ++np) {
                uint32_t kad = stg + (np * 16 + lr) * FPB + kk * 32 + lc;
                uint32_t kh[4], kl[4];
                ldx4(kh, kad);
                ldx4(kl, kad + FTB);
                mma16816(sf[2*np],   qhk, kh[0], kh[2]);
                mma16816(sf[2*np],   qhk, kl[0], kl[2]);
                mma16816(sf[2*np],   qlk, kh[0], kh[2]);
                mma16816(sf[2*np+1], qhk, kh[1], kh[3]);
                mma16816(sf[2*np+1], qhk, kl[1], kl[3]);
                mma16816(sf[2*np+1], qlk, kh[1], kh[3]);
            }
        }

        // ---- bias + online softmax ----
        float mx_lo = -3.0e38f, mx_hi = -3.0e38f;
        #pragma unroll
        for (int n = 0; n < 8; ++n) {
            float2 bl = *(const float2*)(b_lo + kv0 + 8 * n);
            float2 bh2 = *(const float2*)(b_hi + kv0 + 8 * n);
            sf[n][0] = fmaf(sf[n][0], sfac, bscale * bl.x);
            sf[n][1] = fmaf(sf[n][1], sfac, bscale * bl.y);
            sf[n][2] = fmaf(sf[n][2], sfac, bscale * bh2.x);
            sf[n][3] = fmaf(sf[n][3], sfac, bscale * bh2.y);
            mx_lo = fmaxf(mx_lo, fmaxf(sf[n][0], sf[n][1]));
            mx_hi = fmaxf(mx_hi, fmaxf(sf[n][2], sf[n][3]));
        }
        mx_lo = fmaxf(mx_lo, __shfl_xor_sync(0xffffffffu, mx_lo, 1));
        mx_lo = fmaxf(mx_lo, __shfl_xor_sync(0xffffffffu, mx_lo, 2));
        mx_hi = fmaxf(mx_hi, __shfl_xor_sync(0xffffffffu, mx_hi, 1));
        mx_hi = fmaxf(mx_hi, __shfl_xor_sync(0xffffffffu, mx_hi, 2));

        float mn_lo = fmaxf(m_lo, mx_lo), mn_hi = fmaxf(m_hi, mx_hi);
        float al_lo = __expf(m_lo - mn_lo), al_hi = __expf(m_hi - mn_hi);
        m_lo = mn_lo; m_hi = mn_hi;

        float rs_lo = 0.0f, rs_hi = 0.0f;
        #pragma unroll
        for (int n = 0; n < 8; ++n) {
            sf[n][0] = __expf(sf[n][0] - mn_lo);
            sf[n][1] = __expf(sf[n][1] - mn_lo);
            sf[n][2] = __expf(sf[n][2] - mn_hi);
            sf[n][3] = __expf(sf[n][3] - mn_hi);
            rs_lo += sf[n][0] + sf[n][1];
            rs_hi += sf[n][2] + sf[n][3];
        }
        rs_lo += __shfl_xor_sync(0xffffffffu, rs_lo, 1);
        rs_lo += __shfl_xor_sync(0xffffffffu, rs_lo, 2);
        rs_hi += __shfl_xor_sync(0xffffffffu, rs_hi, 1);
        rs_hi += __shfl_xor_sync(0xffffffffu, rs_hi, 2);
        l_lo = l_lo * al_lo + rs_lo;
        l_hi = l_hi * al_hi + rs_hi;

        #pragma unroll
        for (int n = 0; n < 8; ++n) {
            o[n][0] *= al_lo; o[n][1] *= al_lo;
            o[n][2] *= al_hi; o[n][3] *= al_hi;
        }

        // ---- O += P V (P split in registers, V split in smem) ----
        #pragma unroll
        for (int ks = 0; ks < 4; ++ks) {
            uint32_t ph[4], pl[4];
            split2(sf[2*ks][0],   sf[2*ks][1],   ph[0], pl[0]);
            split2(sf[2*ks][2],   sf[2*ks][3],   ph[1], pl[1]);
            split2(sf[2*ks+1][0], sf[2*ks+1][1], ph[2], pl[2]);
            split2(sf[2*ks+1][2], sf[2*ks+1][3], ph[3], pl[3]);
            #pragma unroll
            for (int db = 0; db < 4; ++db) {
                uint32_t vad = stg + 2*FTB + (ks * 16 + lr) * FPB + db * 32 + lc;
                uint32_t vh[4], vl[4];
                ldx4t(vh, vad);
                ldx4t(vl, vad + FTB);
                mma16816(o[2*db],   ph, vh[0], vh[1]);
                mma16816(o[2*db],   ph, vl[0], vl[1]);
                mma16816(o[2*db],   pl, vh[0], vh[1]);
                mma16816(o[2*db+1], ph, vh[2], vh[3]);
                mma16816(o[2*db+1], ph, vl[2], vl[3]);
                mma16816(o[2*db+1], pl, vh[2], vh[3]);
            }
        }

        __syncthreads();
        if (it + 2 < 16) kv_load(s, (it + 2) * 64);
    }

    // ---- normalize + write split bf16 ctx ----
    const float il = 1.0f / l_lo, ih = 1.0f / l_hi;
    const int gq = q0 + wq0 + rl;
    const size_t row_lo = ((size_t)b * CS + gq) * CD + (size_t)h * CDK + 2 * (lane & 3);
    const size_t row_hi = row_lo + (size_t)8 * CD;
    #pragma unroll
    for (int n = 0; n < 8; ++n) {
        uint32_t hh, ll;
        split2(o[n][0] * il, o[n][1] * il, hh, ll);
        *(uint32_t*)&Chi[row_lo + 8 * n] = hh;
        *(uint32_t*)&Clo[row_lo + 8 * n] = ll;
        split2(o[n][2] * ih, o[n][3] * ih, hh, ll);
        *(uint32_t*)&Chi[row_hi + 8 * n] = hh;
        *(uint32_t*)&Clo[row_hi + 8 * n] = ll;
    }
}

// =====================================================================
// launch
// =====================================================================
extern "C" void kernel_launch(void* const* d_in, const int* in_sizes, int n_in,
                              void* d_out, int out_size) {
    (void)in_sizes; (void)n_in; (void)out_size;
    const float* X   = (const float*)d_in[0];
    const float* bLL = (const float*)d_in[1];
    const float* Wq  = (const float*)d_in[2];
    const float* Wk  = (const float*)d_in[3];
    const float* Wv  = (const float*)d_in[4];
    const float* Wo  = (const float*)d_in[5];
    const float* btr = (const float*)d_in[6];
    float* out = (float*)d_out;

    __nv_bfloat16 *xhi, *xlo, *qhi, *qlo, *khi, *klo, *vhi, *vlo, *chi, *clo, *wthi, *wtlo;
    cudaGetSymbolAddress((void**)&xhi,  g_xhi);
    cudaGetSymbolAddress((void**)&xlo,  g_xlo);
    cudaGetSymbolAddress((void**)&qhi,  g_qhi);
    cudaGetSymbolAddress((void**)&qlo,  g_qlo);
    cudaGetSymbolAddress((void**)&khi,  g_khi);
    cudaGetSymbolAddress((void**)&klo,  g_klo);
    cudaGetSymbolAddress((void**)&vhi,  g_vhi);
    cudaGetSymbolAddress((void**)&vlo,  g_vlo);
    cudaGetSymbolAddress((void**)&chi,  g_chi);
    cudaGetSymbolAddress((void**)&clo,  g_clo);
    cudaGetSymbolAddress((void**)&wthi, g_wthi);
    cudaGetSymbolAddress((void**)&wtlo, g_wtlo);

    cudaFuncSetAttribute(gemm_mma_kernel<true>,  cudaFuncAttributeMaxDynamicSharedMemorySize, GSMEM);
    cudaFuncSetAttribute(gemm_mma_kernel<false>, cudaFuncAttributeMaxDynamicSharedMemorySize, GSMEM);
    cudaFuncSetAttribute(flasht_kernel, cudaFuncAttributeMaxDynamicSharedMemorySize, FL_SMEM);

    const int n4x = (CM * CD) / 4;
    const dim3 tsg(32, 32), tsb(32, 8);
    const dim3 gg(CD / 128, CM / 128);   // (8, 128)

    // X -> split bf16
    split_kernel<<<(n4x + 255) / 256, 256>>>((const float4*)X,
        (uint32_t*)xhi, (uint32_t*)xlo, n4x);

    // Q/K/V projections -> split bf16 outputs
    tsplit_kernel<<<tsg, tsb>>>(Wq, wthi, wtlo);
    gemm_mma_kernel<true><<<gg, 256, GSMEM>>>(xhi, xlo, wthi, wtlo, nullptr, qhi, qlo);
    tsplit_kernel<<<tsg, tsb>>>(Wk, wthi, wtlo);
    gemm_mma_kernel<true><<<gg, 256, GSMEM>>>(xhi, xlo, wthi, wtlo, nullptr, khi, klo);
    tsplit_kernel<<<tsg, tsb>>>(Wv, wthi, wtlo);
    gemm_mma_kernel<true><<<gg, 256, GSMEM>>>(xhi, xlo, wthi, wtlo, nullptr, vhi, vlo);

    // attention (tensor-core flash) -> split bf16 ctx
    flasht_kernel<<<dim3(CS / 128, CH, CB), 256, FL_SMEM>>>(
        qhi, qlo, khi, klo, vhi, vlo, bLL, btr, chi, clo);

    // output projection -> fp32 out
    tsplit_kernel<<<tsg, tsb>>>(Wo, wthi, wtlo);
    gemm_mma_kernel<false><<<gg, 256, GSMEM>>>(chi, clo, wthi, wtlo, out, nullptr, nullptr);
}